// round 1
// baseline (speedup 1.0000x reference)
#include <cuda_runtime.h>
#include <cuda_bf16.h>
#include <math.h>

// Problem constants (capacities; runtime sizes read from in_sizes)
#define MAXN 100000
#define MAXE 1000000
#define HF   64          // hidden features
#define SCAN_BLK 1024

// ---------------- scratch (device globals; no allocation allowed) -------------
__device__ __align__(16) float g_degw[MAXN];
__device__ __align__(16) float g_dis[MAXN];
__device__ __align__(16) int   g_cnt[MAXN];
__device__ __align__(16) int   g_cnt2[MAXN];
__device__ __align__(16) int   g_bscan[MAXN];
__device__ __align__(16) int   g_bsum[256];
__device__ __align__(16) int   g_offs[MAXN + 1];
__device__ __align__(16) int   g_ssrc[MAXE];
__device__ __align__(16) float g_snorm[MAXE];
__device__ __align__(16) float g_tmp[(size_t)MAXN * HF];
__device__ __align__(16) float g_ha [(size_t)MAXN * HF];
__device__ __align__(16) float g_hb [(size_t)MAXN * HF];
__device__ __align__(16) float g_m[MAXN];
__device__ __align__(16) float g_den[MAXN];
__device__ __align__(16) float g_num[MAXN];
__device__ __align__(16) float g_nw[MAXN];
__device__ __align__(16) float g_s[256 * HF];
__device__ __align__(16) float g_wsum[256];

// ---------------- setup kernels ----------------------------------------------

__global__ void k_init_nodes(int n) {
    int i = blockIdx.x * blockDim.x + threadIdx.x;
    if (i >= n) return;
    g_degw[i] = 1.0f;          // self-loop weight
    g_cnt[i]  = 0;
    g_cnt2[i] = 0;
    g_m[i]    = -1.0f;         // below any edge weight (ew in [0,1))
    g_den[i]  = 0.0f;
    g_num[i]  = 0.0f;
}

__global__ void k_init_graphs(int bn) {
    int i = blockIdx.x * blockDim.x + threadIdx.x;
    if (i < bn * HF) g_s[i] = 0.0f;
    if (i < bn)      g_wsum[i] = 0.0f;
}

// histogram by col (degree weight + count) and per-node max edge weight
__global__ void k_edge_pass1(const int* __restrict__ row, const int* __restrict__ col,
                             const float* __restrict__ ew, int e) {
    int i = blockIdx.x * blockDim.x + threadIdx.x;
    if (i >= e) return;
    int r = row[i], c = col[i];
    float w = ew[i];
    atomicAdd(&g_degw[c], w);
    atomicAdd(&g_cnt[c], 1);
    int wb = __float_as_int(w);             // w >= 0 -> int-ordered
    atomicMax((int*)&g_m[r], wb);
    atomicMax((int*)&g_m[c], wb);
}

__global__ void k_node_dis(int n) {
    int i = blockIdx.x * blockDim.x + threadIdx.x;
    if (i >= n) return;
    g_dis[i] = rsqrtf(g_degw[i]);           // deg >= 1 always
}

// softmax-weighted (temperature 0.05) incident-edge accumulation
__global__ void k_edge_exp(const int* __restrict__ row, const int* __restrict__ col,
                           const float* __restrict__ ew, int e) {
    int i = blockIdx.x * blockDim.x + threadIdx.x;
    if (i >= e) return;
    int r = row[i], c = col[i];
    float w = ew[i];
    float ar = __expf((w - g_m[r]) * 20.0f);   // 1/0.05
    float ac = __expf((w - g_m[c]) * 20.0f);
    atomicAdd(&g_den[r], ar);
    atomicAdd(&g_num[r], w * ar);
    atomicAdd(&g_den[c], ac);
    atomicAdd(&g_num[c], w * ac);
}

__global__ void k_node_nw(int n) {
    int i = blockIdx.x * blockDim.x + threadIdx.x;
    if (i >= n) return;
    float d = g_den[i];
    g_nw[i] = (d > 0.0f) ? g_num[i] / fmaxf(d, 1e-16f) : 0.0f;
}

// ---- exclusive scan of g_cnt -> g_offs ----
__global__ void k_scan1(int n) {
    __shared__ int sh[SCAN_BLK];
    int i = blockIdx.x * SCAN_BLK + threadIdx.x;
    int v = (i < n) ? g_cnt[i] : 0;
    sh[threadIdx.x] = v;
    __syncthreads();
    for (int off = 1; off < SCAN_BLK; off <<= 1) {
        int t = (threadIdx.x >= off) ? sh[threadIdx.x - off] : 0;
        __syncthreads();
        sh[threadIdx.x] += t;
        __syncthreads();
    }
    if (i < n) g_bscan[i] = sh[threadIdx.x];
    if (threadIdx.x == SCAN_BLK - 1) g_bsum[blockIdx.x] = sh[threadIdx.x];
}

__global__ void k_scan2(int nb) {
    if (threadIdx.x == 0) {
        int run = 0;
        for (int b = 0; b < nb; b++) { int t = g_bsum[b]; g_bsum[b] = run; run += t; }
    }
}

__global__ void k_scan3(int n, int e) {
    int i = blockIdx.x * blockDim.x + threadIdx.x;
    if (i < n) g_offs[i] = g_bsum[i / SCAN_BLK] + g_bscan[i] - g_cnt[i];
    if (i == 0) g_offs[n] = e;
}

// scatter edges into destination-sorted order; precompute edge norm
__global__ void k_edge_scatter(const int* __restrict__ row, const int* __restrict__ col,
                               const float* __restrict__ ew, int e) {
    int i = blockIdx.x * blockDim.x + threadIdx.x;
    if (i >= e) return;
    int r = row[i], c = col[i];
    int p = g_offs[c] + atomicAdd(&g_cnt2[c], 1);
    g_ssrc[p] = r;
    g_snorm[p] = g_dis[r] * ew[i] * g_dis[c];
}

// ---------------- GEMM: [n,64] @ [64,64], optional LeakyReLU on A load --------
template <bool LEAKY>
__global__ void k_gemm64(const float* __restrict__ A, const float* __restrict__ W,
                         float* __restrict__ C, int n) {
    __shared__ float As[64][65];
    __shared__ float Ws[64][64];
    int brow = blockIdx.x * 64;
    for (int i = threadIdx.x; i < 4096; i += 256) {
        int rr = i >> 6, cc = i & 63;
        Ws[rr][cc] = W[i];
        int gr = brow + rr;
        float v = (gr < n) ? A[(size_t)gr * HF + cc] : 0.0f;
        if (LEAKY) v = (v > 0.0f) ? v : 0.01f * v;
        As[rr][cc] = v;
    }
    __syncthreads();
    int r0 = (threadIdx.x >> 4) * 4;       // 16 row-groups
    int c0 = (threadIdx.x & 15) * 4;       // 16 col-groups
    float acc[4][4] = {};
#pragma unroll
    for (int k = 0; k < 64; k++) {
        float a0 = As[r0 + 0][k], a1 = As[r0 + 1][k], a2 = As[r0 + 2][k], a3 = As[r0 + 3][k];
        float4 w4 = *(const float4*)&Ws[k][c0];
        acc[0][0] += a0 * w4.x; acc[0][1] += a0 * w4.y; acc[0][2] += a0 * w4.z; acc[0][3] += a0 * w4.w;
        acc[1][0] += a1 * w4.x; acc[1][1] += a1 * w4.y; acc[1][2] += a1 * w4.z; acc[1][3] += a1 * w4.w;
        acc[2][0] += a2 * w4.x; acc[2][1] += a2 * w4.y; acc[2][2] += a2 * w4.z; acc[2][3] += a2 * w4.w;
        acc[3][0] += a3 * w4.x; acc[3][1] += a3 * w4.y; acc[3][2] += a3 * w4.z; acc[3][3] += a3 * w4.w;
    }
#pragma unroll
    for (int i = 0; i < 4; i++) {
        int gr = brow + r0 + i;
        if (gr < n) {
            float4 o = make_float4(acc[i][0], acc[i][1], acc[i][2], acc[i][3]);
            *(float4*)&C[(size_t)gr * HF + c0] = o;
        }
    }
}

// ---------------- per-node segmented aggregation (warp per node) --------------
__global__ void k_aggregate(const float* __restrict__ tmp, const float* __restrict__ bias,
                            float* __restrict__ out, int n) {
    int gt = blockIdx.x * blockDim.x + threadIdx.x;
    int node = gt >> 5;
    int lane = gt & 31;
    if (node >= n) return;
    float d = g_dis[node];
    float sc = d * d;
    float2 self = ((const float2*)(tmp + (size_t)node * HF))[lane];
    float ax = sc * self.x;
    float ay = sc * self.y;
    int p = g_offs[node], end = g_offs[node + 1];
    for (; p < end; ++p) {
        int s = g_ssrc[p];
        float nv = g_snorm[p];
        float2 v = ((const float2*)(tmp + (size_t)s * HF))[lane];
        ax += nv * v.x;
        ay += nv * v.y;
    }
    float2 bb = ((const float2*)bias)[lane];
    float2 o; o.x = ax + bb.x; o.y = ay + bb.y;
    ((float2*)(out + (size_t)node * HF))[lane] = o;
}

// ---------------- weighted pooling (warp per node) -----------------------------
__global__ void k_pool(const float* __restrict__ h3, const int* __restrict__ batch, int n) {
    int gt = blockIdx.x * blockDim.x + threadIdx.x;
    int node = gt >> 5;
    int lane = gt & 31;
    if (node >= n) return;
    int b = batch[node];
    float w = g_nw[node];
    if (lane == 0) atomicAdd(&g_wsum[b], w);
    float2 v = ((const float2*)(h3 + (size_t)node * HF))[lane];
    atomicAdd(&g_s[b * HF + 2 * lane],     v.x * w);
    atomicAdd(&g_s[b * HF + 2 * lane + 1], v.y * w);
}

// ---------------- MLP head: one thread per graph -------------------------------
__global__ void k_head(const float* __restrict__ Wlin, const float* __restrict__ blin,
                       const float* __restrict__ Wout, const float* __restrict__ bout,
                       float* __restrict__ out, int bn) {
    int b = blockIdx.x * blockDim.x + threadIdx.x;
    if (b >= bn) return;
    const int O_PROBS = bn * 10;
    const int O_FEATS = bn * 20;
    const int O_EMB   = O_FEATS + bn * 128;
    const int O_HOUT  = O_EMB + bn * 64;

    float feats[128];
    float ws = fmaxf(g_wsum[b], 1e-16f);
#pragma unroll
    for (int k = 0; k < HF; k++) {
        float sv = g_s[b * HF + k];
        feats[k] = sv;
        feats[HF + k] = sv / ws;
    }
    float emb[64], ho[64];
    for (int j = 0; j < 64; j++) {
        float a = blin[j];
        for (int i = 0; i < 128; i++) a += feats[i] * __ldg(&Wlin[i * 64 + j]);
        emb[j] = a;
        ho[j] = fmaxf(a, 0.0f);
    }
    float lg[10];
    for (int c = 0; c < 10; c++) {
        float a = bout[c];
        for (int j = 0; j < 64; j++) a += ho[j] * __ldg(&Wout[j * 10 + c]);
        lg[c] = a;
    }
    float mx = lg[0];
#pragma unroll
    for (int c = 1; c < 10; c++) mx = fmaxf(mx, lg[c]);
    float ex[10], den = 0.0f;
#pragma unroll
    for (int c = 0; c < 10; c++) { ex[c] = expf(lg[c] - mx); den += ex[c]; }
    float inv = 1.0f / den;

    for (int c = 0; c < 10; c++) {
        out[b * 10 + c] = lg[c];
        out[O_PROBS + b * 10 + c] = ex[c] * inv;
    }
    for (int i = 0; i < 128; i++) out[O_FEATS + b * 128 + i] = feats[i];
    for (int j = 0; j < 64; j++) {
        out[O_EMB  + b * 64 + j] = emb[j];
        out[O_HOUT + b * 64 + j] = ho[j];
    }
}

// -------------------------------------------------------------------------------
extern "C" void kernel_launch(void* const* d_in, const int* in_sizes, int n_in,
                              void* d_out, int out_size) {
    const float* x    = (const float*)d_in[0];
    const int*   ei   = (const int*)  d_in[1];
    const float* ew   = (const float*)d_in[2];
    const int*   batch= (const int*)  d_in[3];
    const float* W1 = (const float*)d_in[4];  const float* b1 = (const float*)d_in[5];
    const float* W2 = (const float*)d_in[6];  const float* b2 = (const float*)d_in[7];
    const float* W3 = (const float*)d_in[8];  const float* b3 = (const float*)d_in[9];
    const float* Wlin = (const float*)d_in[10]; const float* blin = (const float*)d_in[11];
    const float* Wout = (const float*)d_in[12]; const float* bout = (const float*)d_in[13];
    float* out = (float*)d_out;

    int n  = in_sizes[0] / HF;         // 100000
    int e  = in_sizes[2];              // 1000000
    int bn = out_size / 276;           // 10+10+128+64+64 floats per graph

    const int* row = ei;
    const int* col = ei + e;

    float *p_tmp, *p_ha, *p_hb;
    cudaGetSymbolAddress((void**)&p_tmp, g_tmp);
    cudaGetSymbolAddress((void**)&p_ha,  g_ha);
    cudaGetSymbolAddress((void**)&p_hb,  g_hb);

    int nThreads = 256;
    int nBlkN = (n + nThreads - 1) / nThreads;
    int nBlkE = (e + nThreads - 1) / nThreads;
    int nBlkW = ((n * 32) + nThreads - 1) / nThreads;   // warp-per-node kernels
    int nb = (n + SCAN_BLK - 1) / SCAN_BLK;

    // --- setup: normalization, sort-by-destination, smooth-max weights ---
    k_init_nodes<<<nBlkN, nThreads>>>(n);
    k_init_graphs<<<(bn * HF + nThreads - 1) / nThreads, nThreads>>>(bn);
    k_edge_pass1<<<nBlkE, nThreads>>>(row, col, ew, e);
    k_node_dis<<<nBlkN, nThreads>>>(n);
    k_edge_exp<<<nBlkE, nThreads>>>(row, col, ew, e);
    k_scan1<<<nb, SCAN_BLK>>>(n);
    k_scan2<<<1, 32>>>(nb);
    k_scan3<<<(n + 1 + nThreads - 1) / nThreads, nThreads>>>(n, e);
    k_edge_scatter<<<nBlkE, nThreads>>>(row, col, ew, e);
    k_node_nw<<<nBlkN, nThreads>>>(n);

    int gemmBlks = (n + 63) / 64;
    // --- layer 1 ---
    k_gemm64<false><<<gemmBlks, 256>>>(x, W1, p_tmp, n);
    k_aggregate<<<nBlkW, nThreads>>>(p_tmp, b1, p_ha, n);
    // --- layer 2 (leaky fused into A load) ---
    k_gemm64<true><<<gemmBlks, 256>>>(p_ha, W2, p_tmp, n);
    k_aggregate<<<nBlkW, nThreads>>>(p_tmp, b2, p_hb, n);
    // --- layer 3 ---
    k_gemm64<true><<<gemmBlks, 256>>>(p_hb, W3, p_tmp, n);
    k_aggregate<<<nBlkW, nThreads>>>(p_tmp, b3, p_ha, n);

    // --- pooling + head ---
    k_pool<<<nBlkW, nThreads>>>(p_ha, batch, n);
    k_head<<<(bn + 127) / 128, 128>>>(Wlin, blin, Wout, bout, out, bn);
}